// round 1
// baseline (speedup 1.0000x reference)
#include <cuda_runtime.h>

#define B_TOT 2048
#define LN    128
#define CDIM  128
#define NH    4
#define HD    32
#define SCALEF 0.17677669529663687f   // 32^-0.5

// ------------------------- device scratch (no allocs allowed) ---------------
__device__ float g_q [B_TOT*NH*LN*HD];   // [b][h][l][c], q pre-scaled
__device__ float g_k [B_TOT*NH*LN*HD];
__device__ float g_v [B_TOT*NH*LN*HD];
__device__ float g_oh[B_TOT*LN*CDIM];    // [b][l][h*HD+c]

// =============================================================================
// K1: qkv = x @ qkv_w.T + qkv_b ; split into q (scaled), k, v with [b][h][l][c]
// One block per window b. 256 threads, 8x8 register tiles, 3 column chunks.
// =============================================================================
__global__ __launch_bounds__(256) void qkv_kernel(const float* __restrict__ x,
                                                  const float* __restrict__ w,
                                                  const float* __restrict__ bias) {
    extern __shared__ float sm[];
    float* xT = sm;               // [k][l] stride 132
    float* ws = sm + 128*132;     // [k][c] stride 132
    const int b  = blockIdx.x;
    const int t  = threadIdx.x;
    const int tx = t & 15, ty = t >> 4;

    const float* xb = x + b*LN*CDIM;
    for (int rep = 0; rep < 64; rep++) {
        int idx = rep*256 + t;
        int l = idx >> 7, k = idx & 127;
        xT[k*132 + l] = xb[idx];
    }

    for (int cc = 0; cc < 3; cc++) {
        __syncthreads();
        const float* wb = w + cc*128*128;
        for (int rep = 0; rep < 64; rep++) {
            int idx = rep*256 + t;
            int c = idx >> 7, k = idx & 127;
            ws[k*132 + c] = wb[idx];
        }
        __syncthreads();

        float acc[8][8];
        #pragma unroll
        for (int p = 0; p < 8; p++)
            #pragma unroll
            for (int q = 0; q < 8; q++) acc[p][q] = 0.f;

        #pragma unroll 4
        for (int kk = 0; kk < 128; kk++) {
            float4 xa = *(const float4*)(xT + kk*132 + ty*8);
            float4 xc = *(const float4*)(xT + kk*132 + ty*8 + 4);
            float4 wa = *(const float4*)(ws + kk*132 + tx*8);
            float4 wc = *(const float4*)(ws + kk*132 + tx*8 + 4);
            float xv[8] = {xa.x,xa.y,xa.z,xa.w,xc.x,xc.y,xc.z,xc.w};
            float wv[8] = {wa.x,wa.y,wa.z,wa.w,wc.x,wc.y,wc.z,wc.w};
            #pragma unroll
            for (int p = 0; p < 8; p++)
                #pragma unroll
                for (int q = 0; q < 8; q++) acc[p][q] += xv[p]*wv[q];
        }

        float* arr = (cc == 0) ? g_q : ((cc == 1) ? g_k : g_v);
        float scl  = (cc == 0) ? SCALEF : 1.0f;
        #pragma unroll
        for (int ri = 0; ri < 8; ri++) {
            int l = ty*8 + ri;
            #pragma unroll
            for (int g = 0; g < 2; g++) {
                int col = tx*8 + g*4;
                int hh = col >> 5, ch = col & 31;
                float4 v;
                v.x = (acc[ri][g*4+0] + bias[cc*128 + col + 0]) * scl;
                v.y = (acc[ri][g*4+1] + bias[cc*128 + col + 1]) * scl;
                v.z = (acc[ri][g*4+2] + bias[cc*128 + col + 2]) * scl;
                v.w = (acc[ri][g*4+3] + bias[cc*128 + col + 3]) * scl;
                *(float4*)(arr + ((b*NH + hh)*LN + l)*HD + ch) = v;
            }
        }
    }
}

// =============================================================================
// K2: fused attention per (b, h).
// attn[i][j] = q_i.k_j + q_i.tab_k[ridx] + k_j.tab_q[ridx] + mask[b%128][i][j]
// softmax over j ; out[i][c] = sum_j attn*(v_j[c]) + sum_pj A2*tab_v[ridx][c]
// 256 threads: thread t -> row i = t&127, j-half = t>>7 (64 j's each).
// attn stored in smem (reusing the staged mask tile, stride 129).
// =============================================================================
__global__ __launch_bounds__(256) void attn_kernel(const float* __restrict__ mask,
                                                   const float* __restrict__ rpe) {
    extern __shared__ float sm[];
    float* k_s = sm;                   // 128*32
    float* v_s = k_s + 128*32;         // 128*32
    float* tq  = v_s + 128*32;         // 225*33 (scaled by SCALEF)
    float* tk  = tq  + 225*33;         // 225*33
    float* tv  = tk  + 225*33;         // 225*33
    float* msk = tv  + 225*33;         // 128*129  (mask -> logits -> probs)
    float* ob  = msk + 128*129;        // 128*33 output combine
    float* red = ob  + 128*33;         // 512 reduction scratch

    const int b = blockIdx.x, h = blockIdx.y;
    const int t = threadIdx.x;
    const int i    = t & 127;
    const int half = t >> 7;

    // ---- stage k, v ----
    {
        const float4* kg = (const float4*)(g_k + ((b*NH + h)*LN)*HD);
        const float4* vg = (const float4*)(g_v + ((b*NH + h)*LN)*HD);
        float4* k4 = (float4*)k_s;
        float4* v4 = (float4*)v_s;
        #pragma unroll
        for (int r = 0; r < 4; r++) { k4[r*256 + t] = kg[r*256 + t];
                                      v4[r*256 + t] = vg[r*256 + t]; }
    }
    // ---- stage rpe tables for this head (225 x 96 -> three 225x32, pad 33) ----
    for (int idx = t; idx < 225*96; idx += 256) {
        int tt = idx / 96;
        int u  = idx - tt*96;
        float val = rpe[tt*384 + h*96 + u];
        if      (u < 32) tq[tt*33 + u]      = val * SCALEF;
        else if (u < 64) tk[tt*33 + u - 32] = val;
        else             tv[tt*33 + u - 64] = val;
    }
    // ---- stage mask (window = b % 128) ----
    {
        const float* mg = mask + (b & 127)*LN*LN;
        for (int idx = t; idx < LN*LN; idx += 256) {
            int ii = idx >> 7, j = idx & 127;
            msk[ii*129 + j] = mg[idx];
        }
    }
    // ---- q row into registers ----
    float qreg[32];
    {
        const float4* qg = (const float4*)(g_q + ((b*NH + h)*LN + i)*HD);
        #pragma unroll
        for (int c4 = 0; c4 < 8; c4++) {
            float4 v = qg[c4];
            qreg[c4*4+0] = v.x; qreg[c4*4+1] = v.y;
            qreg[c4*4+2] = v.z; qreg[c4*4+3] = v.w;
        }
    }
    __syncthreads();

    const int hi = i >> 4;         // (i/2)/8
    const int wi = (i >> 1) & 7;   // (i/2)%8

    // ---- logits: accumulate into msk (which already holds the mask) ----
    for (int pjj = 0; pjj < 32; pjj++) {
        int pj = half*32 + pjj;
        int j0 = pj*2, j1 = j0 + 1;
        int ridx = (hi - (pj >> 3) + 7)*15 + (wi - (pj & 7) + 7);
        const float* tkr = tk + ridx*33;
        const float* tqr = tq + ridx*33;
        float qk0 = 0.f, qk1 = 0.f, qr = 0.f, kr0 = 0.f, kr1 = 0.f;
        #pragma unroll
        for (int c4 = 0; c4 < 8; c4++) {
            float4 k0 = *(const float4*)(k_s + j0*HD + c4*4);
            float4 k1 = *(const float4*)(k_s + j1*HD + c4*4);
            float t0 = tkr[c4*4+0], t1 = tkr[c4*4+1], t2 = tkr[c4*4+2], t3 = tkr[c4*4+3];
            float s0 = tqr[c4*4+0], s1 = tqr[c4*4+1], s2 = tqr[c4*4+2], s3 = tqr[c4*4+3];
            float q0 = qreg[c4*4+0], q1 = qreg[c4*4+1], q2 = qreg[c4*4+2], q3 = qreg[c4*4+3];
            qk0 += q0*k0.x + q1*k0.y + q2*k0.z + q3*k0.w;
            qk1 += q0*k1.x + q1*k1.y + q2*k1.z + q3*k1.w;
            qr  += q0*t0   + q1*t1   + q2*t2   + q3*t3;
            kr0 += k0.x*s0 + k0.y*s1 + k0.z*s2 + k0.w*s3;
            kr1 += k1.x*s0 + k1.y*s1 + k1.z*s2 + k1.w*s3;
        }
        msk[i*129 + j0] += qk0 + qr + kr0;
        msk[i*129 + j1] += qk1 + qr + kr1;
    }

    // ---- softmax over j (row i), cross-half reduce via smem ----
    float* row = msk + i*129 + half*64;
    float lm = -3.0e38f;
    for (int jj = 0; jj < 64; jj++) lm = fmaxf(lm, row[jj]);
    red[half*128 + i] = lm;
    __syncthreads();
    float m = fmaxf(red[i], red[128 + i]);
    float ls = 0.f;
    for (int jj = 0; jj < 64; jj++) {
        float e = __expf(row[jj] - m);
        row[jj] = e;
        ls += e;
    }
    red[256 + half*128 + i] = ls;
    __syncthreads();
    float rinv = 1.0f / (red[256 + i] + red[384 + i]);

    // ---- output: out[i][c] = sum attn*v + sum A2*tab_v (normalize at end) ----
    float acc[32];
    #pragma unroll
    for (int c = 0; c < 32; c++) acc[c] = 0.f;

    for (int pjj = 0; pjj < 32; pjj++) {
        int pj = half*32 + pjj;
        int j0 = pj*2, j1 = j0 + 1;
        int ridx = (hi - (pj >> 3) + 7)*15 + (wi - (pj & 7) + 7);
        const float* tvr = tv + ridx*33;
        float a0 = msk[i*129 + j0];
        float a1 = msk[i*129 + j1];
        float A2 = a0 + a1;
        #pragma unroll
        for (int c4 = 0; c4 < 8; c4++) {
            float4 v0 = *(const float4*)(v_s + j0*HD + c4*4);
            float4 v1 = *(const float4*)(v_s + j1*HD + c4*4);
            acc[c4*4+0] += a0*v0.x + a1*v1.x + A2*tvr[c4*4+0];
            acc[c4*4+1] += a0*v0.y + a1*v1.y + A2*tvr[c4*4+1];
            acc[c4*4+2] += a0*v0.z + a1*v1.z + A2*tvr[c4*4+2];
            acc[c4*4+3] += a0*v0.w + a1*v1.w + A2*tvr[c4*4+3];
        }
    }
    #pragma unroll
    for (int c = 0; c < 32; c++) acc[c] *= rinv;

    // ---- combine halves, coalesced store to g_oh[b][i][h*32+c] ----
    if (half == 0) {
        #pragma unroll
        for (int c = 0; c < 32; c++) ob[i*33 + c] = acc[c];
    }
    __syncthreads();
    if (half == 1) {
        #pragma unroll
        for (int c = 0; c < 32; c++) ob[i*33 + c] += acc[c];
    }
    __syncthreads();
    {
        float* dst = g_oh + b*LN*CDIM;
        #pragma unroll
        for (int r = 0; r < 16; r++) {
            int fl = r*256 + t;
            int ii = fl >> 5, c = fl & 31;
            dst[ii*CDIM + h*HD + c] = ob[ii*33 + c];
        }
    }
}

// =============================================================================
// K3: out = oh @ proj_w.T + proj_b   (one 128x128x128 GEMM per window)
// =============================================================================
__global__ __launch_bounds__(256) void proj_kernel(const float* __restrict__ w,
                                                   const float* __restrict__ bias,
                                                   float* __restrict__ out) {
    extern __shared__ float sm[];
    float* xT = sm;               // [k][l] stride 132
    float* ws = sm + 128*132;     // [k][c] stride 132
    const int b  = blockIdx.x;
    const int t  = threadIdx.x;
    const int tx = t & 15, ty = t >> 4;

    const float* xb = g_oh + b*LN*CDIM;
    for (int rep = 0; rep < 64; rep++) {
        int idx = rep*256 + t;
        int l = idx >> 7, k = idx & 127;
        xT[k*132 + l] = xb[idx];
        int c = l; // same decomposition for weights
        ws[k*132 + c] = w[idx];
    }
    __syncthreads();

    float acc[8][8];
    #pragma unroll
    for (int p = 0; p < 8; p++)
        #pragma unroll
        for (int q = 0; q < 8; q++) acc[p][q] = 0.f;

    #pragma unroll 4
    for (int kk = 0; kk < 128; kk++) {
        float4 xa = *(const float4*)(xT + kk*132 + ty*8);
        float4 xc = *(const float4*)(xT + kk*132 + ty*8 + 4);
        float4 wa = *(const float4*)(ws + kk*132 + tx*8);
        float4 wc = *(const float4*)(ws + kk*132 + tx*8 + 4);
        float xv[8] = {xa.x,xa.y,xa.z,xa.w,xc.x,xc.y,xc.z,xc.w};
        float wv[8] = {wa.x,wa.y,wa.z,wa.w,wc.x,wc.y,wc.z,wc.w};
        #pragma unroll
        for (int p = 0; p < 8; p++)
            #pragma unroll
            for (int q = 0; q < 8; q++) acc[p][q] += xv[p]*wv[q];
    }

    #pragma unroll
    for (int ri = 0; ri < 8; ri++) {
        int l = ty*8 + ri;
        #pragma unroll
        for (int g = 0; g < 2; g++) {
            int col = tx*8 + g*4;
            float4 v;
            v.x = acc[ri][g*4+0] + bias[col + 0];
            v.y = acc[ri][g*4+1] + bias[col + 1];
            v.z = acc[ri][g*4+2] + bias[col + 2];
            v.w = acc[ri][g*4+3] + bias[col + 3];
            *(float4*)(out + (b*LN + l)*CDIM + col) = v;
        }
    }
}

// =============================================================================
extern "C" void kernel_launch(void* const* d_in, const int* in_sizes, int n_in,
                              void* d_out, int out_size) {
    const float* x        = (const float*)d_in[0];
    const float* attn_msk = (const float*)d_in[1];
    const float* qkv_w    = (const float*)d_in[2];
    const float* qkv_b    = (const float*)d_in[3];
    const float* rpe      = (const float*)d_in[4];
    const float* proj_w   = (const float*)d_in[5];
    const float* proj_b   = (const float*)d_in[6];
    float* out = (float*)d_out;

    const int smem_gemm = 2*128*132*sizeof(float);                         // 135168
    const int smem_attn = (128*32*2 + 3*225*33 + 128*129 + 128*33 + 512)*sizeof(float); // 206860

    cudaFuncSetAttribute(qkv_kernel,  cudaFuncAttributeMaxDynamicSharedMemorySize, smem_gemm);
    cudaFuncSetAttribute(attn_kernel, cudaFuncAttributeMaxDynamicSharedMemorySize, smem_attn);
    cudaFuncSetAttribute(proj_kernel, cudaFuncAttributeMaxDynamicSharedMemorySize, smem_gemm);

    qkv_kernel <<<B_TOT, 256, smem_gemm>>>(x, qkv_w, qkv_b);
    attn_kernel<<<dim3(B_TOT, NH), 256, smem_attn>>>(attn_msk, rpe);
    proj_kernel<<<B_TOT, 256, smem_gemm>>>(proj_w, proj_b, out);
}

// round 4
// speedup vs baseline: 1.4078x; 1.4078x over previous
#include <cuda_runtime.h>

#define B_TOT 2048
#define LN    128
#define CDIM  128
#define NH    4
#define HD    32
#define SCALEF 0.17677669529663687f   // 32^-0.5

typedef unsigned long long ull;

// ---------- f32x2 packed helpers (sm_103a) ----------
__device__ __forceinline__ void fma2(ull& d, ull a, ull b) {
    asm("fma.rn.f32x2 %0, %1, %2, %0;" : "+l"(d) : "l"(a), "l"(b));
}
__device__ __forceinline__ ull pk2(float x, float y) {
    ull r; asm("mov.b64 %0, {%1, %2};" : "=l"(r) : "f"(x), "f"(y)); return r;
}
__device__ __forceinline__ float2 up2(ull u) {
    float2 f; asm("mov.b64 {%0, %1}, %2;" : "=f"(f.x), "=f"(f.y) : "l"(u)); return f;
}

// ------------------------- device scratch (no allocs allowed) ---------------
__device__ float g_q [B_TOT*NH*LN*HD];   // [b][h][l][c], q pre-scaled
__device__ float g_k [B_TOT*NH*LN*HD];
__device__ float g_v [B_TOT*NH*LN*HD];
__device__ float g_oh[B_TOT*LN*CDIM];    // [b][l][h*HD+c]

// =============================================================================
// K1: qkv = x @ qkv_w.T + qkv_b. Full x tile in smem, weights double-buffered
// in 32-wide K chunks -> 101KB smem -> 2 CTAs/SM. f32x2 packed inner loop.
// =============================================================================
__global__ __launch_bounds__(256, 2) void qkv_kernel(const float* __restrict__ x,
                                                     const float* __restrict__ w,
                                                     const float* __restrict__ bias) {
    extern __shared__ float sm[];
    float* xT = sm;                 // [128][132]
    float* ws = sm + 128*132;       // [2][32][132]
    const int b  = blockIdx.x;
    const int t  = threadIdx.x;
    const int tx = t & 15, ty = t >> 4;

    const float* xb = x + (size_t)b*LN*CDIM;
    #pragma unroll
    for (int rep = 0; rep < 64; rep++) {
        int idx = rep*256 + t;
        xT[(idx & 127)*132 + (idx >> 7)] = xb[idx];
    }

    for (int cc = 0; cc < 3; cc++) {
        const float* wb = w + cc*128*128;
        // stage K-chunk 0
        #pragma unroll
        for (int rep = 0; rep < 16; rep++) {
            int idx = rep*256 + t;
            int c = idx >> 5, k = idx & 31;
            ws[k*132 + c] = wb[c*128 + k];
        }
        __syncthreads();

        ull acc2[8][4];
        #pragma unroll
        for (int p = 0; p < 8; p++) {
            #pragma unroll
            for (int q2 = 0; q2 < 4; q2++) acc2[p][q2] = 0ull;
        }

        for (int kc = 0; kc < 4; kc++) {
            const float* wcur = ws + (kc & 1)*32*132;
            #pragma unroll
            for (int kk = 0; kk < 32; kk++) {
                int krow = kc*32 + kk;
                float4 xa = *(const float4*)(xT + krow*132 + ty*8);
                float4 xc = *(const float4*)(xT + krow*132 + ty*8 + 4);
                ulonglong2 wa = *(const ulonglong2*)(wcur + kk*132 + tx*8);
                ulonglong2 wc = *(const ulonglong2*)(wcur + kk*132 + tx*8 + 4);
                float xf[8] = {xa.x,xa.y,xa.z,xa.w,xc.x,xc.y,xc.z,xc.w};
                #pragma unroll
                for (int p = 0; p < 8; p++) {
                    ull xp = pk2(xf[p], xf[p]);
                    fma2(acc2[p][0], xp, wa.x);
                    fma2(acc2[p][1], xp, wa.y);
                    fma2(acc2[p][2], xp, wc.x);
                    fma2(acc2[p][3], xp, wc.y);
                }
            }
            if (kc < 3) {
                float* wnext = ws + ((kc + 1) & 1)*32*132;
                int kbase = (kc + 1)*32;
                #pragma unroll
                for (int rep = 0; rep < 16; rep++) {
                    int idx = rep*256 + t;
                    int c = idx >> 5, k = idx & 31;
                    wnext[k*132 + c] = wb[c*128 + kbase + k];
                }
            }
            __syncthreads();
        }

        float* arr = (cc == 0) ? g_q : ((cc == 1) ? g_k : g_v);
        float scl  = (cc == 0) ? SCALEF : 1.0f;
        #pragma unroll
        for (int ri = 0; ri < 8; ri++) {
            int l = ty*8 + ri;
            #pragma unroll
            for (int g = 0; g < 2; g++) {
                int col = tx*8 + g*4;
                int hh = col >> 5, ch = col & 31;
                float2 e0 = up2(acc2[ri][g*2+0]);
                float2 e1 = up2(acc2[ri][g*2+1]);
                float4 v;
                v.x = (e0.x + bias[cc*128 + col + 0]) * scl;
                v.y = (e0.y + bias[cc*128 + col + 1]) * scl;
                v.z = (e1.x + bias[cc*128 + col + 2]) * scl;
                v.w = (e1.y + bias[cc*128 + col + 3]) * scl;
                *(float4*)(arr + (((size_t)b*NH + hh)*LN + l)*HD + ch) = v;
            }
        }
    }
}

// =============================================================================
// K2: fused attention per (b, h). 512 threads: jq = tid>>7 (j quarter),
// i = tid&127. Logits live in registers (att[32]); mask loaded straight from
// global (contiguous 128B per thread). f32x2 packed dot products everywhere.
// =============================================================================
__global__ __launch_bounds__(512, 1) void attn_kernel(const float* __restrict__ mask,
                                                      const float* __restrict__ rpe) {
    extern __shared__ float sm[];
    float* k_s  = sm;                   // [128][32]
    float* v_s  = k_s + 4096;           // [128][32]
    float* tq   = v_s + 4096;           // [225][36] (scaled by SCALEF)
    float* tk   = tq  + 8100;           // [225][36]
    float* tv   = tk  + 8100;           // [225][36]
    float* buf0 = tv  + 8100;           // [128][36]
    float* buf1 = buf0 + 4608;          // [128][36]
    float* redm = buf1 + 4608;          // [512]
    float* reds = redm + 512;           // [512]

    const int b = blockIdx.x, h = blockIdx.y;
    const int t  = threadIdx.x;
    const int i  = t & 127;
    const int jq = t >> 7;              // 0..3, owns j in [jq*32, jq*32+32)

    // ---- stage k, v (128*32 floats = 1024 float4; 2 reps x 512 threads) ----
    {
        const float4* kg = (const float4*)(g_k + (((size_t)b*NH + h)*LN)*HD);
        const float4* vg = (const float4*)(g_v + (((size_t)b*NH + h)*LN)*HD);
        float4* k4 = (float4*)k_s;
        float4* v4 = (float4*)v_s;
        #pragma unroll
        for (int r = 0; r < 2; r++) { k4[r*512 + t] = kg[r*512 + t];
                                      v4[r*512 + t] = vg[r*512 + t]; }
    }
    // ---- stage rpe tables for this head (225 x 96 -> three 225x36-padded) ----
    for (int idx = t; idx < 225*96; idx += 512) {
        int tt = idx / 96;
        int u  = idx - tt*96;
        float val = rpe[tt*384 + h*96 + u];
        if      (u < 32) tq[tt*36 + u]      = val * SCALEF;
        else if (u < 64) tk[tt*36 + u - 32] = val;
        else             tv[tt*36 + u - 64] = val;
    }
    // ---- q row into packed registers ----
    ull qv[16];
    {
        const ulonglong2* qg = (const ulonglong2*)(g_q + (((size_t)b*NH + h)*LN + i)*HD);
        #pragma unroll
        for (int u = 0; u < 8; u++) { ulonglong2 z = qg[u]; qv[2*u] = z.x; qv[2*u+1] = z.y; }
    }
    // ---- att init from mask (contiguous 128B per thread, full sectors) ----
    float att[32];
    {
        const float4* mp = (const float4*)(mask + (size_t)(b & 127)*LN*LN + i*LN + jq*32);
        #pragma unroll
        for (int u = 0; u < 8; u++) {
            float4 m4 = mp[u];
            att[u*4+0] = m4.x; att[u*4+1] = m4.y; att[u*4+2] = m4.z; att[u*4+3] = m4.w;
        }
    }
    __syncthreads();

    const int hi = i >> 4;
    const int wi = (i >> 1) & 7;

    // ---- logits ----
    #pragma unroll
    for (int jj = 0; jj < 16; jj++) {
        int pj = jq*16 + jj;
        int ridx = (hi - (pj >> 3) + 7)*15 + (wi - (pj & 7) + 7);
        const ulonglong2* k0p = (const ulonglong2*)(k_s + pj*2*HD);
        const ulonglong2* k1p = k0p + 8;
        const ulonglong2* tkp = (const ulonglong2*)(tk + ridx*36);
        const ulonglong2* tqp = (const ulonglong2*)(tq + ridx*36);
        ull qk0 = 0, qk1 = 0, qr = 0, kr0 = 0, kr1 = 0;
        #pragma unroll
        for (int u = 0; u < 8; u++) {
            ulonglong2 kv0 = k0p[u], kv1 = k1p[u], tkv = tkp[u], tqv = tqp[u];
            ull q0 = qv[2*u], q1 = qv[2*u+1];
            fma2(qk0, q0, kv0.x); fma2(qk0, q1, kv0.y);
            fma2(qk1, q0, kv1.x); fma2(qk1, q1, kv1.y);
            fma2(qr,  q0, tkv.x); fma2(qr,  q1, tkv.y);
            fma2(kr0, kv0.x, tqv.x); fma2(kr0, kv0.y, tqv.y);
            fma2(kr1, kv1.x, tqv.x); fma2(kr1, kv1.y, tqv.y);
        }
        float2 f0 = up2(qk0), f1 = up2(qk1), fr = up2(qr), g0 = up2(kr0), g1 = up2(kr1);
        float qrs = fr.x + fr.y;
        att[2*jj]   += f0.x + f0.y + qrs + g0.x + g0.y;
        att[2*jj+1] += f1.x + f1.y + qrs + g1.x + g1.y;
    }

    // ---- softmax over full row (4 jq threads share row i) ----
    float m = att[0];
    #pragma unroll
    for (int u = 1; u < 32; u++) m = fmaxf(m, att[u]);
    redm[jq*128 + i] = m;
    __syncthreads();
    m = fmaxf(fmaxf(redm[i], redm[128 + i]), fmaxf(redm[256 + i], redm[384 + i]));
    float ls = 0.f;
    #pragma unroll
    for (int u = 0; u < 32; u++) { float e = __expf(att[u] - m); att[u] = e; ls += e; }
    reds[jq*128 + i] = ls;
    __syncthreads();
    float rinv = 1.0f / (reds[i] + reds[128 + i] + reds[256 + i] + reds[384 + i]);

    // ---- output: acc2 packed over c ----
    ull acc2[16];
    #pragma unroll
    for (int u = 0; u < 16; u++) acc2[u] = 0ull;

    #pragma unroll
    for (int jj = 0; jj < 16; jj++) {
        int pj = jq*16 + jj;
        int ridx = (hi - (pj >> 3) + 7)*15 + (wi - (pj & 7) + 7);
        const ulonglong2* v0p = (const ulonglong2*)(v_s + pj*2*HD);
        const ulonglong2* v1p = v0p + 8;
        const ulonglong2* tvp = (const ulonglong2*)(tv + ridx*36);
        float a0 = att[2*jj], a1 = att[2*jj+1];
        ull ap0 = pk2(a0, a0), ap1 = pk2(a1, a1), ap2 = pk2(a0 + a1, a0 + a1);
        #pragma unroll
        for (int u = 0; u < 8; u++) {
            ulonglong2 vv0 = v0p[u], vv1 = v1p[u], tvv = tvp[u];
            fma2(acc2[2*u],   ap0, vv0.x); fma2(acc2[2*u+1], ap0, vv0.y);
            fma2(acc2[2*u],   ap1, vv1.x); fma2(acc2[2*u+1], ap1, vv1.y);
            fma2(acc2[2*u],   ap2, tvv.x); fma2(acc2[2*u+1], ap2, tvv.y);
        }
    }

    float o[32];
    #pragma unroll
    for (int u = 0; u < 16; u++) {
        float2 f = up2(acc2[u]);
        o[2*u] = f.x * rinv; o[2*u+1] = f.y * rinv;
    }

    // ---- reduce 4 partial sums per row, store to g_oh ----
    if (jq == 2) {
        for (int c = 0; c < 8; c++) *(float4*)(buf0 + i*36 + c*4) = *(float4*)(o + c*4);
    }
    if (jq == 3) {
        for (int c = 0; c < 8; c++) *(float4*)(buf1 + i*36 + c*4) = *(float4*)(o + c*4);
    }
    __syncthreads();
    if (jq == 0) {
        for (int c = 0; c < 32; c++) o[c] += buf0[i*36 + c];
    }
    if (jq == 1) {
        for (int c = 0; c < 32; c++) o[c] += buf1[i*36 + c];
    }
    __syncthreads();
    if (jq == 1) {
        for (int c = 0; c < 8; c++) *(float4*)(buf0 + i*36 + c*4) = *(float4*)(o + c*4);
    }
    __syncthreads();
    if (jq == 0) {
        float* dst = g_oh + ((size_t)b*LN + i)*CDIM + h*HD;
        #pragma unroll
        for (int c = 0; c < 8; c++) {
            float4 v;
            v.x = o[c*4+0] + buf0[i*36 + c*4+0];
            v.y = o[c*4+1] + buf0[i*36 + c*4+1];
            v.z = o[c*4+2] + buf0[i*36 + c*4+2];
            v.w = o[c*4+3] + buf0[i*36 + c*4+3];
            *(float4*)dst = v; dst += 4;
        }
    }
}

// =============================================================================
// K3: out = oh @ proj_w.T + proj_b (same scheme as K1, single weight block)
// =============================================================================
__global__ __launch_bounds__(256, 2) void proj_kernel(const float* __restrict__ w,
                                                      const float* __restrict__ bias,
                                                      float* __restrict__ out) {
    extern __shared__ float sm[];
    float* xT = sm;                 // [128][132]
    float* ws = sm + 128*132;       // [2][32][132]
    const int b  = blockIdx.x;
    const int t  = threadIdx.x;
    const int tx = t & 15, ty = t >> 4;

    const float* xb = g_oh + (size_t)b*LN*CDIM;
    #pragma unroll
    for (int rep = 0; rep < 64; rep++) {
        int idx = rep*256 + t;
        xT[(idx & 127)*132 + (idx >> 7)] = xb[idx];
    }
    #pragma unroll
    for (int rep = 0; rep < 16; rep++) {
        int idx = rep*256 + t;
        int c = idx >> 5, k = idx & 31;
        ws[k*132 + c] = w[c*128 + k];
    }
    __syncthreads();

    ull acc2[8][4];
    #pragma unroll
    for (int p = 0; p < 8; p++) {
        #pragma unroll
        for (int q2 = 0; q2 < 4; q2++) acc2[p][q2] = 0ull;
    }

    for (int kc = 0; kc < 4; kc++) {
        const float* wcur = ws + (kc & 1)*32*132;
        #pragma unroll
        for (int kk = 0; kk < 32; kk++) {
            int krow = kc*32 + kk;
            float4 xa = *(const float4*)(xT + krow*132 + ty*8);
            float4 xc = *(const float4*)(xT + krow*132 + ty*8 + 4);
            ulonglong2 wa = *(const ulonglong2*)(wcur + kk*132 + tx*8);
            ulonglong2 wc = *(const ulonglong2*)(wcur + kk*132 + tx*8 + 4);
            float xf[8] = {xa.x,xa.y,xa.z,xa.w,xc.x,xc.y,xc.z,xc.w};
            #pragma unroll
            for (int p = 0; p < 8; p++) {
                ull xp = pk2(xf[p], xf[p]);
                fma2(acc2[p][0], xp, wa.x);
                fma2(acc2[p][1], xp, wa.y);
                fma2(acc2[p][2], xp, wc.x);
                fma2(acc2[p][3], xp, wc.y);
            }
        }
        if (kc < 3) {
            float* wnext = ws + ((kc + 1) & 1)*32*132;
            int kbase = (kc + 1)*32;
            #pragma unroll
            for (int rep = 0; rep < 16; rep++) {
                int idx = rep*256 + t;
                int c = idx >> 5, k = idx & 31;
                wnext[k*132 + c] = w[c*128 + kbase + k];
            }
        }
        __syncthreads();
    }

    #pragma unroll
    for (int ri = 0; ri < 8; ri++) {
        int l = ty*8 + ri;
        #pragma unroll
        for (int g = 0; g < 2; g++) {
            int col = tx*8 + g*4;
            float2 e0 = up2(acc2[ri][g*2+0]);
            float2 e1 = up2(acc2[ri][g*2+1]);
            float4 v;
            v.x = e0.x + bias[col + 0];
            v.y = e0.y + bias[col + 1];
            v.z = e1.x + bias[col + 2];
            v.w = e1.y + bias[col + 3];
            *(float4*)(out + ((size_t)b*LN + l)*CDIM + col) = v;
        }
    }
}

// =============================================================================
extern "C" void kernel_launch(void* const* d_in, const int* in_sizes, int n_in,
                              void* d_out, int out_size) {
    const float* x        = (const float*)d_in[0];
    const float* attn_msk = (const float*)d_in[1];
    const float* qkv_w    = (const float*)d_in[2];
    const float* qkv_b    = (const float*)d_in[3];
    const float* rpe      = (const float*)d_in[4];
    const float* proj_w   = (const float*)d_in[5];
    const float* proj_b   = (const float*)d_in[6];
    float* out = (float*)d_out;

    const int smem_gemm = (128*132 + 2*32*132)*sizeof(float);                 // 101376
    const int smem_attn = (4096*2 + 3*8100 + 2*4608 + 1024)*sizeof(float);    // 170928

    cudaFuncSetAttribute(qkv_kernel,  cudaFuncAttributeMaxDynamicSharedMemorySize, smem_gemm);
    cudaFuncSetAttribute(attn_kernel, cudaFuncAttributeMaxDynamicSharedMemorySize, smem_attn);
    cudaFuncSetAttribute(proj_kernel, cudaFuncAttributeMaxDynamicSharedMemorySize, smem_gemm);

    qkv_kernel <<<B_TOT, 256, smem_gemm>>>(x, qkv_w, qkv_b);
    attn_kernel<<<dim3(B_TOT, NH), 512, smem_attn>>>(attn_msk, rpe);
    proj_kernel<<<B_TOT, 256, smem_gemm>>>(proj_w, proj_b, out);
}